// round 5
// baseline (speedup 1.0000x reference)
#include <cuda_runtime.h>

#define TPB 128
#define DD  64
#define MM  256
#define JT  16            // j-columns per register tile (8 packed f32x2 accumulators)
#define NJT (MM / JT)     // 16 tiles

// dynamic shared: At[64][256] + b[256] + pAt[256] + pivot[64]
#define SMEM_FLOATS (DD * MM + MM + MM + DD)

extern __shared__ float s_mem[];

// packed dual-fma: d = a*b + d per f32 lane (bitwise == 2x fmaf)
__device__ __forceinline__ void fma2(unsigned long long& d,
                                     unsigned long long a,
                                     unsigned long long b)
{
    asm("fma.rn.f32x2 %0, %1, %2, %0;" : "+l"(d) : "l"(a), "l"(b));
}

__device__ __forceinline__ unsigned long long bcast2(float x)
{
    unsigned long long r;
    unsigned int u = __float_as_uint(x);
    asm("mov.b64 %0, {%1, %1};" : "=l"(r) : "r"(u));
    return r;
}

union F4U2 { float4 v; unsigned long long u[2]; };

__global__ void __launch_bounds__(TPB, 3)
constrain_kernel(const float* __restrict__ z,
                 const float* __restrict__ pivot,
                 const float* __restrict__ At,
                 const float* __restrict__ b,
                 float* __restrict__ out)
{
    float* At_sh  = s_mem;                 // [64][256] row d contiguous
    float* b_sh   = s_mem + DD * MM;       // [256]
    float* pAt_sh = b_sh + MM;             // [256]
    float* piv_sh = pAt_sh + MM;           // [64]

    const int tid = threadIdx.x;

    // ---- stage At (4096 float4, 32 per thread), pivot, b ----
    {
        const float4* g4 = reinterpret_cast<const float4*>(At);
        float4* s4 = reinterpret_cast<float4*>(At_sh);
        #pragma unroll
        for (int i = 0; i < (DD * MM / 4) / TPB; ++i)
            s4[tid + i * TPB] = g4[tid + i * TPB];
    }
    if (tid < DD) piv_sh[tid] = pivot[tid];
    b_sh[tid]       = b[tid];
    b_sh[tid + TPB] = b[tid + TPB];
    __syncthreads();

    // ---- pAt = pivot @ At  (each thread: 2 columns) ----
    #pragma unroll 1
    for (int jj = 0; jj < MM / TPB; ++jj) {
        const int j = tid + jj * TPB;
        float s = 0.0f;
        #pragma unroll
        for (int d = 0; d < DD; ++d)
            s = fmaf(piv_sh[d], At_sh[d * MM + j], s);
        pAt_sh[j] = s;
    }
    __syncthreads();

    // ---- per-row work: row = global thread id ----
    const long long row = (long long)blockIdx.x * TPB + tid;
    const float4* zg4 = reinterpret_cast<const float4*>(z + row * DD);

    float zr[DD];
    #pragma unroll
    for (int i = 0; i < DD / 4; ++i) {
        float4 t = zg4[i];
        zr[4 * i + 0] = t.x; zr[4 * i + 1] = t.y;
        zr[4 * i + 2] = t.z; zr[4 * i + 3] = t.w;
    }

    // running argmax of alpha = sa/nd over qualified j, via cross-multiplication
    float best_sa = 0.0f;   // init -> alpha 0 (matches max(alpha*ind) lower bound)
    float best_nd = 1.0f;
    int   any = 0;

    #pragma unroll 1
    for (int jt = 0; jt < NJT; ++jt) {
        unsigned long long acc2[JT / 2];   // 8 packed accumulators = 16 columns
        #pragma unroll
        for (int k = 0; k < JT / 2; ++k) acc2[k] = 0ULL;  // {0.0f, 0.0f}

        const float4* a4 = reinterpret_cast<const float4*>(At_sh + jt * JT);
        #pragma unroll
        for (int d = 0; d < DD; ++d) {
            const unsigned long long zdd = bcast2(zr[d]);
            F4U2 m0, m1, m2, m3;
            m0.v = a4[d * (MM / 4) + 0];
            m1.v = a4[d * (MM / 4) + 1];
            m2.v = a4[d * (MM / 4) + 2];
            m3.v = a4[d * (MM / 4) + 3];
            fma2(acc2[0], zdd, m0.u[0]);
            fma2(acc2[1], zdd, m0.u[1]);
            fma2(acc2[2], zdd, m1.u[0]);
            fma2(acc2[3], zdd, m1.u[1]);
            fma2(acc2[4], zdd, m2.u[0]);
            fma2(acc2[5], zdd, m2.u[1]);
            fma2(acc2[6], zdd, m3.u[0]);
            fma2(acc2[7], zdd, m3.u[1]);
        }

        // unpack + epilogue for these 16 columns
        float acc[JT];
        #pragma unroll
        for (int k = 0; k < JT / 2; ++k) {
            unsigned int lo, hi;
            asm("mov.b64 {%0, %1}, %2;" : "=r"(lo), "=r"(hi) : "l"(acc2[k]));
            acc[2 * k + 0] = __uint_as_float(lo);
            acc[2 * k + 1] = __uint_as_float(hi);
        }

        #pragma unroll
        for (int k = 0; k < JT; ++k) {
            const int j = jt * JT + k;
            const float s  = acc[k];
            const float sa = s - b_sh[j];                    // sign_arg
            // -denom = -min(pAt - s, -1e-9) = max(s - pAt, 1e-9)  (> 0)
            const float nd = fmaxf(s - pAt_sh[j], 1e-9f);
            const int q = (sa >= 0.0f);
            any |= q;
            // alpha = sa/nd ; take if qualified and sa/nd > best_sa/best_nd
            const bool take = q && (sa * best_nd > best_sa * nd);
            best_sa = take ? sa : best_sa;
            best_nd = take ? nd : best_nd;
        }
    }

    const float c = any ? (best_sa / best_nd) : 0.0f;

    float4* o4 = reinterpret_cast<float4*>(out + row * DD);
    #pragma unroll
    for (int i = 0; i < DD / 4; ++i) {
        float4 r;
        r.x = fmaf(c, piv_sh[4 * i + 0] - zr[4 * i + 0], zr[4 * i + 0]);
        r.y = fmaf(c, piv_sh[4 * i + 1] - zr[4 * i + 1], zr[4 * i + 1]);
        r.z = fmaf(c, piv_sh[4 * i + 2] - zr[4 * i + 2], zr[4 * i + 2]);
        r.w = fmaf(c, piv_sh[4 * i + 3] - zr[4 * i + 3], zr[4 * i + 3]);
        o4[i] = r;
    }
}

extern "C" void kernel_launch(void* const* d_in, const int* in_sizes, int n_in,
                              void* d_out, int out_size)
{
    const float* z     = (const float*)d_in[0];  // [N, 64]
    const float* pivot = (const float*)d_in[1];  // [64]
    const float* At    = (const float*)d_in[2];  // [64, 256]
    const float* b     = (const float*)d_in[3];  // [256]
    float* out = (float*)d_out;                  // [N, 64]

    const int N = in_sizes[0] / DD;              // 262144
    const int smem_bytes = SMEM_FLOATS * (int)sizeof(float);  // 67840

    // >48KB dynamic shared opt-in (idempotent; not a stream op, capture-safe)
    cudaFuncSetAttribute(constrain_kernel,
                         cudaFuncAttributeMaxDynamicSharedMemorySize, smem_bytes);

    constrain_kernel<<<N / TPB, TPB, smem_bytes>>>(z, pivot, At, b, out);
}

// round 6
// speedup vs baseline: 1.3909x; 1.3909x over previous
#include <cuda_runtime.h>

#define TPB 128
#define RPT 2             // rows per thread
#define DD  64
#define MM  256
#define JT  16            // j-columns per register tile (8 packed f32x2 accumulators)
#define NJT (MM / JT)     // 16 tiles

// dynamic shared: At[64][256] + b[256] + pAt[256] + pivot[64]
#define SMEM_FLOATS (DD * MM + MM + MM + DD)

extern __shared__ float s_mem[];

// packed dual-fma: d = a*b + d per f32 lane (bitwise == 2x fmaf)
__device__ __forceinline__ void fma2(unsigned long long& d,
                                     unsigned long long a,
                                     unsigned long long b)
{
    asm("fma.rn.f32x2 %0, %1, %2, %0;" : "+l"(d) : "l"(a), "l"(b));
}

__device__ __forceinline__ unsigned long long bcast2(float x)
{
    unsigned long long r;
    unsigned int u = __float_as_uint(x);
    asm("mov.b64 %0, {%1, %1};" : "=l"(r) : "r"(u));
    return r;
}

union F4U2 { float4 v; unsigned long long u[2]; };

// epilogue over 16 columns: update running argmax of alpha = sa/nd
__device__ __forceinline__ void epi_tile(const unsigned long long* acc2,
                                         const float* b_sh, const float* pAt_sh,
                                         int jbase,
                                         float& best_sa, float& best_nd, int& any)
{
    float acc[JT];
    #pragma unroll
    for (int k = 0; k < JT / 2; ++k) {
        unsigned int lo, hi;
        asm("mov.b64 {%0, %1}, %2;" : "=r"(lo), "=r"(hi) : "l"(acc2[k]));
        acc[2 * k + 0] = __uint_as_float(lo);
        acc[2 * k + 1] = __uint_as_float(hi);
    }
    #pragma unroll
    for (int k = 0; k < JT; ++k) {
        const int j = jbase + k;
        const float s  = acc[k];
        const float sa = s - b_sh[j];                    // sign_arg
        // -denom = -min(pAt - s, -1e-9) = max(s - pAt, 1e-9)  (> 0)
        const float nd = fmaxf(s - pAt_sh[j], 1e-9f);
        const int q = (sa >= 0.0f);
        any |= q;
        const bool take = q && (sa * best_nd > best_sa * nd);
        best_sa = take ? sa : best_sa;
        best_nd = take ? nd : best_nd;
    }
}

__global__ void __launch_bounds__(TPB, 2)
constrain_kernel(const float* __restrict__ z,
                 const float* __restrict__ pivot,
                 const float* __restrict__ At,
                 const float* __restrict__ b,
                 float* __restrict__ out)
{
    float* At_sh  = s_mem;                 // [64][256] row d contiguous
    float* b_sh   = s_mem + DD * MM;       // [256]
    float* pAt_sh = b_sh + MM;             // [256]
    float* piv_sh = pAt_sh + MM;           // [64]

    const int tid = threadIdx.x;

    // ---- stage At (4096 float4, 32 per thread), pivot, b ----
    {
        const float4* g4 = reinterpret_cast<const float4*>(At);
        float4* s4 = reinterpret_cast<float4*>(At_sh);
        #pragma unroll
        for (int i = 0; i < (DD * MM / 4) / TPB; ++i)
            s4[tid + i * TPB] = g4[tid + i * TPB];
    }
    if (tid < DD) piv_sh[tid] = pivot[tid];
    b_sh[tid]       = b[tid];
    b_sh[tid + TPB] = b[tid + TPB];
    __syncthreads();

    // ---- pAt = pivot @ At  (each thread: 2 columns) ----
    #pragma unroll 1
    for (int jj = 0; jj < MM / TPB; ++jj) {
        const int j = tid + jj * TPB;
        float s = 0.0f;
        #pragma unroll
        for (int d = 0; d < DD; ++d)
            s = fmaf(piv_sh[d], At_sh[d * MM + j], s);
        pAt_sh[j] = s;
    }
    __syncthreads();

    // ---- per-thread rows: r0 = blk*256 + tid, r1 = r0 + 128 (both coalesced) ----
    const long long row0 = (long long)blockIdx.x * (TPB * RPT) + tid;
    const long long row1 = row0 + TPB;

    float zr0[DD], zr1[DD];
    {
        const float4* zg0 = reinterpret_cast<const float4*>(z + row0 * DD);
        const float4* zg1 = reinterpret_cast<const float4*>(z + row1 * DD);
        #pragma unroll
        for (int i = 0; i < DD / 4; ++i) {
            float4 t0 = zg0[i];
            zr0[4 * i + 0] = t0.x; zr0[4 * i + 1] = t0.y;
            zr0[4 * i + 2] = t0.z; zr0[4 * i + 3] = t0.w;
            float4 t1 = zg1[i];
            zr1[4 * i + 0] = t1.x; zr1[4 * i + 1] = t1.y;
            zr1[4 * i + 2] = t1.z; zr1[4 * i + 3] = t1.w;
        }
    }

    float best_sa0 = 0.0f, best_nd0 = 1.0f;
    float best_sa1 = 0.0f, best_nd1 = 1.0f;
    int any0 = 0, any1 = 0;

    #pragma unroll 1
    for (int jt = 0; jt < NJT; ++jt) {
        unsigned long long acc0[JT / 2], acc1[JT / 2];
        #pragma unroll
        for (int k = 0; k < JT / 2; ++k) { acc0[k] = 0ULL; acc1[k] = 0ULL; }

        const float4* a4 = reinterpret_cast<const float4*>(At_sh + jt * JT);
        #pragma unroll
        for (int d = 0; d < DD; ++d) {
            const unsigned long long zdd0 = bcast2(zr0[d]);
            const unsigned long long zdd1 = bcast2(zr1[d]);
            F4U2 m0, m1, m2, m3;
            m0.v = a4[d * (MM / 4) + 0];
            m1.v = a4[d * (MM / 4) + 1];
            m2.v = a4[d * (MM / 4) + 2];
            m3.v = a4[d * (MM / 4) + 3];
            fma2(acc0[0], zdd0, m0.u[0]);  fma2(acc1[0], zdd1, m0.u[0]);
            fma2(acc0[1], zdd0, m0.u[1]);  fma2(acc1[1], zdd1, m0.u[1]);
            fma2(acc0[2], zdd0, m1.u[0]);  fma2(acc1[2], zdd1, m1.u[0]);
            fma2(acc0[3], zdd0, m1.u[1]);  fma2(acc1[3], zdd1, m1.u[1]);
            fma2(acc0[4], zdd0, m2.u[0]);  fma2(acc1[4], zdd1, m2.u[0]);
            fma2(acc0[5], zdd0, m2.u[1]);  fma2(acc1[5], zdd1, m2.u[1]);
            fma2(acc0[6], zdd0, m3.u[0]);  fma2(acc1[6], zdd1, m3.u[0]);
            fma2(acc0[7], zdd0, m3.u[1]);  fma2(acc1[7], zdd1, m3.u[1]);
        }

        epi_tile(acc0, b_sh, pAt_sh, jt * JT, best_sa0, best_nd0, any0);
        epi_tile(acc1, b_sh, pAt_sh, jt * JT, best_sa1, best_nd1, any1);
    }

    const float c0 = any0 ? (best_sa0 / best_nd0) : 0.0f;
    const float c1 = any1 ? (best_sa1 / best_nd1) : 0.0f;

    float4* o0 = reinterpret_cast<float4*>(out + row0 * DD);
    float4* o1 = reinterpret_cast<float4*>(out + row1 * DD);
    #pragma unroll
    for (int i = 0; i < DD / 4; ++i) {
        float4 r0, r1;
        r0.x = fmaf(c0, piv_sh[4 * i + 0] - zr0[4 * i + 0], zr0[4 * i + 0]);
        r0.y = fmaf(c0, piv_sh[4 * i + 1] - zr0[4 * i + 1], zr0[4 * i + 1]);
        r0.z = fmaf(c0, piv_sh[4 * i + 2] - zr0[4 * i + 2], zr0[4 * i + 2]);
        r0.w = fmaf(c0, piv_sh[4 * i + 3] - zr0[4 * i + 3], zr0[4 * i + 3]);
        o0[i] = r0;
        r1.x = fmaf(c1, piv_sh[4 * i + 0] - zr1[4 * i + 0], zr1[4 * i + 0]);
        r1.y = fmaf(c1, piv_sh[4 * i + 1] - zr1[4 * i + 1], zr1[4 * i + 1]);
        r1.z = fmaf(c1, piv_sh[4 * i + 2] - zr1[4 * i + 2], zr1[4 * i + 2]);
        r1.w = fmaf(c1, piv_sh[4 * i + 3] - zr1[4 * i + 3], zr1[4 * i + 3]);
        o1[i] = r1;
    }
}

extern "C" void kernel_launch(void* const* d_in, const int* in_sizes, int n_in,
                              void* d_out, int out_size)
{
    const float* z     = (const float*)d_in[0];  // [N, 64]
    const float* pivot = (const float*)d_in[1];  // [64]
    const float* At    = (const float*)d_in[2];  // [64, 256]
    const float* b     = (const float*)d_in[3];  // [256]
    float* out = (float*)d_out;                  // [N, 64]

    const int N = in_sizes[0] / DD;              // 262144
    const int smem_bytes = SMEM_FLOATS * (int)sizeof(float);  // 67840

    cudaFuncSetAttribute(constrain_kernel,
                         cudaFuncAttributeMaxDynamicSharedMemorySize, smem_bytes);

    constrain_kernel<<<N / (TPB * RPT), TPB, smem_bytes>>>(z, pivot, At, b, out);
}